// round 2
// baseline (speedup 1.0000x reference)
#include <cuda_runtime.h>
#include <cuda_bf16.h>
#include <cstdint>

typedef unsigned long long u64;

#define N_PTS 16384
#define M_CTR 4096
#define NNB   32
#define R2F   0.04f
#define NROWS (M_CTR*NNB)
#define KP    144
#define CAP   256

// ---------------- device scratch (allowed: __device__ globals) ----------
__device__ __align__(16) float4 g_pos4[N_PTS];
__device__ __align__(16) float4 g_center[M_CTR];
__device__ int   g_cols[NROWS];
__device__ __align__(16) float g_W1p[KP*128];
__device__ __align__(16) float g_W2p[KP*128];
__device__ __align__(16) float g_W3p[KP*256];
__device__ __align__(16) float g_A [(size_t)NROWS*KP];
__device__ __align__(16) float g_H1[(size_t)NROWS*KP];
__device__ __align__(16) float g_H2[(size_t)NROWS*KP];
__device__ __align__(16) float g_H3[(size_t)NROWS*256];

// ---------------- f32x2 helpers ----------------------------------------
__device__ __forceinline__ u64 pk(float lo, float hi) {
    u64 r; asm("mov.b64 %0,{%1,%2};" : "=l"(r) : "f"(lo), "f"(hi)); return r;
}
__device__ __forceinline__ void upk(float& lo, float& hi, u64 v) {
    asm("mov.b64 {%0,%1},%2;" : "=f"(lo), "=f"(hi) : "l"(v));
}
__device__ __forceinline__ u64 add2(u64 a, u64 b) {
    u64 r; asm("add.rn.f32x2 %0,%1,%2;" : "=l"(r) : "l"(a), "l"(b)); return r;
}
__device__ __forceinline__ u64 mul2(u64 a, u64 b) {
    u64 r; asm("mul.rn.f32x2 %0,%1,%2;" : "=l"(r) : "l"(a), "l"(b)); return r;
}
__device__ __forceinline__ u64 fma2(u64 a, u64 b, u64 c) {
    u64 r; asm("fma.rn.f32x2 %0,%1,%2,%3;" : "=l"(r) : "l"(a), "l"(b), "l"(c)); return r;
}

// ---------------- prep: pos extract + weight padding (bias folded) -----
__global__ void __launch_bounds__(256) prep_kernel(
    const float* __restrict__ x,
    const float* __restrict__ W1, const float* __restrict__ b1,
    const float* __restrict__ W2, const float* __restrict__ b2,
    const float* __restrict__ W3, const float* __restrict__ b3)
{
    int i = blockIdx.x * 256 + threadIdx.x;          // up to 36864
    if (i < N_PTS) {
        const float* row = x + (size_t)i * 131;
        g_pos4[i] = make_float4(row[0], row[1], row[2], 0.f);
    }
    if (i < KP * 128) {
        int k = i >> 7, j = i & 127;
        g_W1p[i] = (k < 131) ? W1[k * 128 + j] : (k == 131 ? b1[j] : 0.f);
        g_W2p[i] = (k < 128) ? W2[k * 128 + j] : (k == 128 ? b2[j] : 0.f);
    }
    if (i < KP * 256) {
        int k = i >> 8, j = i & 255;
        g_W3p[i] = (k < 128) ? W3[k * 256 + j] : (k == 128 ? b3[j] : 0.f);
    }
}

// pad cols 128..143 of H1/H2 with (1,0,0,...,0): bias column for next GEMM
__global__ void __launch_bounds__(256) pad_kernel() {
    int row = blockIdx.x * 256 + threadIdx.x;
    if (row >= NROWS) return;
    float4* p1 = (float4*)(g_H1 + (size_t)row * KP + 128);
    float4* p2 = (float4*)(g_H2 + (size_t)row * KP + 128);
    float4 one0 = make_float4(1.f, 0.f, 0.f, 0.f);
    float4 z    = make_float4(0.f, 0.f, 0.f, 0.f);
    p1[0] = one0; p1[1] = z; p1[2] = z; p1[3] = z;
    p2[0] = one0; p2[1] = z; p2[2] = z; p2[3] = z;
}

// ---------------- FPS: single CTA, coords in regs, min_d in smem -------
__global__ void __launch_bounds__(512, 1) fps_kernel() {
    extern __shared__ float s_mind[];                 // 16384 floats
    __shared__ float s_rv[16];
    __shared__ int   s_rp[16];
    __shared__ float s_c[3];
    __shared__ int   s_w;

    int tid = threadIdx.x, lane = tid & 31, warp = tid >> 5;

    u64 px[16], py[16], pz[16];
#pragma unroll
    for (int j = 0; j < 16; j++) {
        float4 a = g_pos4[(2 * j) * 512 + tid];
        float4 b = g_pos4[(2 * j + 1) * 512 + tid];
        px[j] = pk(a.x, b.x); py[j] = pk(a.y, b.y); pz[j] = pk(a.z, b.z);
    }
#pragma unroll
    for (int j = 0; j < 32; j++) s_mind[j * 512 + tid] = __int_as_float(0x7f800000);
    if (tid == 0) {
        float4 c0 = g_pos4[0];
        s_c[0] = c0.x; s_c[1] = c0.y; s_c[2] = c0.z;
        g_center[0] = make_float4(c0.x, c0.y, c0.z, 0.f);
    }
    __syncthreads();

    for (int k = 1; k < M_CTR; k++) {
        float cx = s_c[0], cy = s_c[1], cz = s_c[2];
        u64 ncx = pk(-cx, -cx), ncy = pk(-cy, -cy), ncz = pk(-cz, -cz);
        float bestv = -1.f; int bi = 0;
#pragma unroll
        for (int j = 0; j < 16; j++) {
            // p + (-c) is bit-identical to p - c; rn mul/add, order (x2+y2)+z2
            u64 dx = add2(px[j], ncx);
            u64 dy = add2(py[j], ncy);
            u64 dz = add2(pz[j], ncz);
            u64 s  = add2(add2(mul2(dx, dx), mul2(dy, dy)), mul2(dz, dz));
            float d0, d1; upk(d0, d1, s);
            int i0 = (2 * j) * 512 + tid, i1 = i0 + 512;
            float m0 = s_mind[i0], m1 = s_mind[i1];
            if (d0 < m0) { m0 = d0; s_mind[i0] = d0; }
            if (d1 < m1) { m1 = d1; s_mind[i1] = d1; }
            if (m0 > bestv) { bestv = m0; bi = i0; }   // strict >: lowest idx on tie
            if (m1 > bestv) { bestv = m1; bi = i1; }
        }
#pragma unroll
        for (int o = 16; o; o >>= 1) {
            float ov = __shfl_xor_sync(0xffffffffu, bestv, o);
            int   oi = __shfl_xor_sync(0xffffffffu, bi, o);
            if (ov > bestv || (ov == bestv && oi < bi)) { bestv = ov; bi = oi; }
        }
        if (lane == 0) { s_rv[warp] = bestv; s_rp[warp] = bi; }
        __syncthreads();
        if (warp == 0) {
            float v = (lane < 16) ? s_rv[lane] : -2.f;
            int   p = (lane < 16) ? s_rp[lane] : 0x7fffffff;
#pragma unroll
            for (int o = 8; o; o >>= 1) {
                float ov = __shfl_xor_sync(0xffffffffu, v, o);
                int   oi = __shfl_xor_sync(0xffffffffu, p, o);
                if (ov > v || (ov == v && oi < p)) { v = ov; p = oi; }
            }
            if (lane == 0) s_w = p;
        }
        __syncthreads();
        int w = s_w;
        if ((w & 511) == tid) {                       // owner extracts coords
            int j = w >> 9;
            int pr = j >> 1; bool hi = j & 1;
            float X = 0.f, Y = 0.f, Z = 0.f;
#pragma unroll
            for (int jj = 0; jj < 16; jj++) if (jj == pr) {
                float lo, h2;
                upk(lo, h2, px[jj]); X = hi ? h2 : lo;
                upk(lo, h2, py[jj]); Y = hi ? h2 : lo;
                upk(lo, h2, pz[jj]); Z = hi ? h2 : lo;
            }
            s_c[0] = X; s_c[1] = Y; s_c[2] = Z;
            g_center[k] = make_float4(X, Y, Z, 0.f);
        }
        __syncthreads();
    }
}

// ---------------- radius-KNN: 1 warp / center, smem pos tiles ----------
__global__ void __launch_bounds__(128) knn_kernel() {
    extern __shared__ float4 s_t[];                  // 4096 float4 = 64KB
    __shared__ u64 s_list[4][CAP];
    int tid = threadIdx.x, lane = tid & 31, warp = tid >> 5;
    int c = blockIdx.x * 4 + warp;
    float4 ct = g_center[c];

    int cnt = 0;
    for (int tile = 0; tile < 4; tile++) {
        __syncthreads();
        for (int i = tid; i < 4096; i += 128) s_t[i] = g_pos4[tile * 4096 + i];
        __syncthreads();
        for (int i = lane; i < 4096; i += 32) {
            float4 p = s_t[i];
            float dx = __fsub_rn(ct.x, p.x);
            float dy = __fsub_rn(ct.y, p.y);
            float dz = __fsub_rn(ct.z, p.z);
            float d2 = __fadd_rn(__fadd_rn(__fmul_rn(dx, dx), __fmul_rn(dy, dy)),
                                 __fmul_rn(dz, dz));
            bool ok = d2 <= R2F;
            unsigned m = __ballot_sync(0xffffffffu, ok);
            if (ok) {
                int pos = cnt + __popc(m & ((1u << lane) - 1u));
                if (pos < CAP)
                    s_list[warp][pos] =
                        ((u64)__float_as_uint(d2) << 32) | (unsigned)(tile * 4096 + i);
            }
            cnt += __popc(m);
        }
    }
    if (cnt > CAP) cnt = CAP;
    __syncwarp();

    if (cnt <= NNB) {
        int v = (lane < cnt) ? (int)(unsigned)(s_list[warp][lane] & 0xffffffffu) : -1;
        g_cols[c * NNB + lane] = v;
    } else {
        for (int i = lane; i < cnt; i += 32) {
            u64 ki = s_list[warp][i];
            int rank = 0;
            for (int j = 0; j < cnt; j++) rank += (s_list[warp][j] < ki);
            if (rank < NNB)
                g_cols[c * NNB + rank] = (int)(unsigned)(ki & 0xffffffffu);
        }
    }
}

// ---------------- gather: build A[131072 x 144] ------------------------
__global__ void __launch_bounds__(128) gather_kernel(const float* __restrict__ x) {
    int row  = blockIdx.x * 4 + (threadIdx.x >> 5);
    int lane = threadIdx.x & 31;
    int c    = row >> 5;
    int col  = g_cols[row];
    float* a = g_A + (size_t)row * KP;
    float4 v = make_float4(0.f, 0.f, 0.f, 0.f);
    if (col >= 0) {
        const float* xr = x + (size_t)col * 131 + 3 + 4 * lane;
        v = make_float4(xr[0], xr[1], xr[2], xr[3]);
    }
    ((float4*)a)[lane] = v;
    if (lane < 4) {
        float4 e = make_float4(0.f, 0.f, 0.f, 0.f);
        if (lane == 0) {
            if (col >= 0) {
                float4 p = g_pos4[col]; float4 ct = g_center[c];
                e = make_float4(p.x - ct.x, p.y - ct.y, p.z - ct.z, 1.0f);
            } else e = make_float4(0.f, 0.f, 0.f, 1.0f);
        }
        ((float4*)a)[32 + lane] = e;
    }
}

// ---------------- tiled fp32 GEMM + relu, f32x2 packed FMA -------------
// L: 0 = A@W1->H1 (ldc 144), 1 = H1@W2->H2 (ldc 144), 2 = H2@W3->H3 (ldc 256)
template<int L>
__global__ void __launch_bounds__(256) sgemm_kernel() {
    const float* A = (L == 0) ? g_A  : (L == 1) ? g_H1 : g_H2;
    const float* B = (L == 0) ? g_W1p : (L == 1) ? g_W2p : g_W3p;
    float*       C = (L == 0) ? g_H1 : (L == 1) ? g_H2 : g_H3;
    const int ldb = (L == 2) ? 256 : 128;
    const int ldc = (L == 2) ? 256 : KP;

    __shared__ __align__(16) float As[16][132];
    __shared__ __align__(16) float Bs[16][132];
    int t  = threadIdx.x;
    int tx = t & 15, ty = t >> 4;
    size_t bRow = (size_t)blockIdx.x * 128;
    int    bCol = blockIdx.y * 128;

    u64 acc[8][4];
#pragma unroll
    for (int i = 0; i < 8; i++)
#pragma unroll
        for (int p = 0; p < 4; p++) acc[i][p] = 0ull;

    for (int k0 = 0; k0 < KP; k0 += 16) {
#pragma unroll
        for (int e2 = 0; e2 < 2; e2++) {
            int e = t * 2 + e2;                       // 0..511
            int r = e >> 2, c4 = e & 3;               // A: 128 rows x 4 float4
            float4 f = *(const float4*)(A + (bRow + r) * KP + k0 + c4 * 4);
            As[c4 * 4 + 0][r] = f.x; As[c4 * 4 + 1][r] = f.y;
            As[c4 * 4 + 2][r] = f.z; As[c4 * 4 + 3][r] = f.w;
        }
#pragma unroll
        for (int e2 = 0; e2 < 2; e2++) {
            int e = t * 2 + e2;
            int r = e >> 5, c4 = e & 31;              // B: 16 rows x 32 float4
            *(float4*)&Bs[r][c4 * 4] =
                *(const float4*)(B + (size_t)(k0 + r) * ldb + bCol + c4 * 4);
        }
        __syncthreads();
#pragma unroll
        for (int kk = 0; kk < 16; kk++) {
            float a[8]; u64 b[4];
            const u64* bp = (const u64*)&Bs[kk][tx * 8];
#pragma unroll
            for (int p = 0; p < 4; p++) b[p] = bp[p];
#pragma unroll
            for (int i = 0; i < 8; i++) a[i] = As[kk][ty * 8 + i];
#pragma unroll
            for (int i = 0; i < 8; i++) {
                u64 aa = pk(a[i], a[i]);
#pragma unroll
                for (int p = 0; p < 4; p++) acc[i][p] = fma2(aa, b[p], acc[i][p]);
            }
        }
        __syncthreads();
    }
#pragma unroll
    for (int i = 0; i < 8; i++) {
        float* cr = C + (bRow + ty * 8 + i) * (size_t)ldc + bCol + tx * 8;
#pragma unroll
        for (int p = 0; p < 4; p++) {
            float lo, hi; upk(lo, hi, acc[i][p]);
            ((float2*)cr)[p] = make_float2(fmaxf(lo, 0.f), fmaxf(hi, 0.f));
        }
    }
}

// ---------------- masked max-pool ---------------------------------------
__global__ void __launch_bounds__(256) pool_kernel(float* __restrict__ out) {
    int c = blockIdx.x, j = threadIdx.x;
    float acc = __int_as_float(0xff800000);           // -inf
    bool any = false;
#pragma unroll 4
    for (int s = 0; s < NNB; s++) {
        bool v  = g_cols[c * NNB + s] >= 0;
        float h = g_H3[(size_t)(c * NNB + s) * 256 + j];
        if (v) { any = true; acc = fmaxf(acc, h); }
    }
    out[(size_t)c * 256 + j] = any ? acc : 0.0f;
}

// ---------------- launcher ----------------------------------------------
extern "C" void kernel_launch(void* const* d_in, const int* in_sizes, int n_in,
                              void* d_out, int out_size) {
    const float* x  = (const float*)d_in[0];
    const float* W1 = (const float*)d_in[1];
    const float* b1 = (const float*)d_in[2];
    const float* W2 = (const float*)d_in[3];
    const float* b2 = (const float*)d_in[4];
    const float* W3 = (const float*)d_in[5];
    const float* b3 = (const float*)d_in[6];
    float* out = (float*)d_out;

    cudaFuncSetAttribute(fps_kernel, cudaFuncAttributeMaxDynamicSharedMemorySize, 65536);
    cudaFuncSetAttribute(knn_kernel, cudaFuncAttributeMaxDynamicSharedMemorySize, 65536);

    prep_kernel<<<144, 256>>>(x, W1, b1, W2, b2, W3, b3);
    pad_kernel<<<(NROWS + 255) / 256, 256>>>();
    fps_kernel<<<1, 512, 65536>>>();
    knn_kernel<<<M_CTR / 4, 128, 65536>>>();
    gather_kernel<<<NROWS / 4, 128>>>(x);
    sgemm_kernel<0><<<dim3(NROWS / 128, 1), 256>>>();
    sgemm_kernel<1><<<dim3(NROWS / 128, 1), 256>>>();
    sgemm_kernel<2><<<dim3(NROWS / 128, 2), 256>>>();
    pool_kernel<<<M_CTR, 256>>>(out);
}